// round 17
// baseline (speedup 1.0000x reference)
#include <cuda_runtime.h>
#include <cuda_fp16.h>
#include <cstdint>

// Problem constants: B=8192, O=64, D=64, K=64
#define BB   8192
#define OO   64
#define DD   64
#define JJN  65                 // 0 = left-linear, 1..63 cubic, 64 = right-linear
#define SLICE (JJN * 32)        // uint4 entries per d-slice = 2080 (fp16-packed, o-pairs)
#define SLICE_BYTES (SLICE * 16) // 33280
#define PAIRB (2 * SLICE_BYTES)  // 66560 bytes: two consecutive d-slices per DMA
#define NDC  4                  // d-chunks (split-K)
#define DCH  (DD / NDC)         // 16
#define NPAIR (DCH / 2)         // 8 pair-iterations
#define BT   256                // b-tile per CTA
#define NBT  (BB / BT)          // 32

typedef unsigned long long u64;

// Static device scratch
__device__ uint4 g_Ph[DD * SLICE];        // packed cubic coeffs, 2.13 MB
__device__ float g_part[NDC * BB * OO];   // split-K partials, 8 MB

// ---------------------------------------------------------------- asm helpers
__device__ __forceinline__ u64 pk2(float a, float b) {
    u64 r; asm("mov.b64 %0, {%1, %2};" : "=l"(r) : "f"(a), "f"(b)); return r;
}
__device__ __forceinline__ float2 upk2(u64 a) {
    float2 r; asm("mov.b64 {%0, %1}, %2;" : "=f"(r.x), "=f"(r.y) : "l"(a)); return r;
}
__device__ __forceinline__ u64 add2(u64 a, u64 b) {
    u64 d; asm("add.rn.f32x2 %0, %1, %2;" : "=l"(d) : "l"(a), "l"(b)); return d;
}
__device__ __forceinline__ void mbar_init(uint32_t mbar, uint32_t cnt) {
    asm volatile("mbarrier.init.shared.b64 [%0], %1;" :: "r"(mbar), "r"(cnt) : "memory");
}
__device__ __forceinline__ void mbar_expect_tx(uint32_t mbar, uint32_t bytes) {
    asm volatile("mbarrier.arrive.expect_tx.shared::cta.b64 _, [%0], %1;"
                 :: "r"(mbar), "r"(bytes) : "memory");
}
__device__ __forceinline__ void bulk_g2s(uint32_t dst, const void* src, uint32_t bytes,
                                         uint32_t mbar) {
    asm volatile("cp.async.bulk.shared::cta.global.mbarrier::complete_tx::bytes "
                 "[%0], [%1], %2, [%3];"
                 :: "r"(dst), "l"(src), "r"(bytes), "r"(mbar) : "memory");
}
__device__ __forceinline__ void mbar_wait(uint32_t mbar, uint32_t parity) {
    asm volatile(
        "{\n"
        ".reg .pred P;\n"
        "W%=:\n"
        "mbarrier.try_wait.parity.acquire.cta.shared::cta.b64 P, [%0], %1, 0x989680;\n"
        "@P bra D%=;\n"
        "bra W%=;\n"
        "D%=:\n"
        "}"
        :: "r"(mbar), "r"(parity) : "memory");
}
__device__ __forceinline__ void bar_arrive(int id) {
    asm volatile("bar.arrive %0, 512;" :: "r"(id) : "memory");
}
__device__ __forceinline__ void bar_wait(int id) {
    asm volatile("bar.sync %0, 512;" :: "r"(id) : "memory");
}

// ---------------------------------------------------------------- PCHIP (exact reference math)
__device__ __forceinline__ float pchip_end(float d0, float d1) {
    float s = 0.5f * (3.0f * d0 - d1);
    if (s * d0 <= 0.0f) s = 0.0f;
    else if (d0 * d1 < 0.0f && fabsf(s) > 3.0f * fabsf(d0)) s = 3.0f * d0;
    return s;
}
__device__ __forceinline__ float pchip_mid(float dp, float dn) {
    return (dp * dn > 0.0f) ? (2.0f * dp * dn / (dp + dn + 1e-12f)) : 0.0f;
}
__device__ __forceinline__ float4 pchip_emit(int jj, float ya, float yb, float yc, float yd) {
    const float inv_h = 15.75f;     // 63/4 exact
    const float h = 4.0f / 63.0f;
    float dab = (yb - ya) * inv_h;
    float dbc = (yc - yb) * inv_h;
    float dcd = (yd - yc) * inv_h;
    float4 p;
    if (jj == 0) {
        p = make_float4(ya, h * pchip_end(dab, dbc), 0.0f, 0.0f);
    } else if (jj == 64) {
        p = make_float4(yd, h * pchip_end(dcd, dbc), 0.0f, 0.0f);
    } else {
        float y0v, y1v, m0v, m1v;
        if (jj == 1)       { y0v = ya; y1v = yb; m0v = pchip_end(dab, dbc); m1v = pchip_mid(dab, dbc); }
        else if (jj == 63) { y0v = yc; y1v = yd; m0v = pchip_mid(dbc, dcd); m1v = pchip_end(dcd, dbc); }
        else               { y0v = yb; y1v = yc; m0v = pchip_mid(dab, dbc); m1v = pchip_mid(dbc, dcd); }
        float M0 = h * m0v, M1 = h * m1v;
        p.x = y0v;
        p.y = M0;
        p.z = -3.0f * y0v + 3.0f * y1v - 2.0f * M0 - M1;
        p.w =  2.0f * y0v - 2.0f * y1v + M0 + M1;
    }
    return p;
}

// ---------------------------------------------------------------- prep: SINGLE WAVE
// grid (DD, 2) = 128 CTAs, 512 threads. CTA (d, half) loads the full 64x64 y-slice
// (coalesced float4, sy stride 65 -> conflict-free lane reads) and emits jj in
// [0,32] (half 0) or [33,64] (half 1), ~2 jj per warp. One wave => all CTAs
// execute the PDL trigger immediately and prep critical path is ~1 CTA latency.
__global__ __launch_bounds__(512) void kan_prep(const float* __restrict__ coeffs) {
    cudaTriggerProgrammaticLaunchCompletion();

    __shared__ float sy[OO * 65];   // [o][k], padded rows

    const int d    = blockIdx.x;
    const int half = blockIdx.y;
    const int tid  = threadIdx.x;

    // load coeffs[:, d, :] -> sy (64 o-rows x 16 float4, 2 per thread)
    for (int e = tid; e < 1024; e += 512) {
        int o = e >> 4, q = (e & 15) << 2;
        float4 v = *reinterpret_cast<const float4*>(coeffs + (o << 12) + (d << 6) + q);
        float* r = sy + o * 65 + q;
        r[0] = v.x; r[1] = v.y; r[2] = v.z; r[3] = v.w;
    }
    __syncthreads();

    const int w = tid >> 5, lane = tid & 31;
    const int lo = half ? 33 : 0;
    const int hi = half ? 64 : 32;

    for (int jj = lo + w; jj <= hi; jj += 16) {
        int s = (jj == 0) ? 0 : ((jj == 64) ? 60 : min(max(jj - 2, 0), 60));
        const float* r0 = &sy[lane * 65 + s];
        const float* r1 = &sy[(lane + 32) * 65 + s];
        float4 pa = pchip_emit(jj, r0[0], r0[1], r0[2], r0[3]);
        float4 pb = pchip_emit(jj, r1[0], r1[1], r1[2], r1[3]);

        __half2 h0 = __floats2half2_rn(pa.x, pb.x);
        __half2 h1 = __floats2half2_rn(pa.y, pb.y);
        __half2 h2 = __floats2half2_rn(pa.z, pb.z);
        __half2 h3 = __floats2half2_rn(pa.w, pb.w);
        uint4 q;
        q.x = *reinterpret_cast<uint32_t*>(&h0);
        q.y = *reinterpret_cast<uint32_t*>(&h1);
        q.z = *reinterpret_cast<uint32_t*>(&h2);
        q.w = *reinterpret_cast<uint32_t*>(&h3);
        g_Ph[d * SLICE + (jj << 5) + lane] = q;
    }
}

// ---------------------------------------------------------------- main contraction (R16, frozen)
// grid (NBT, NDC) = (32, 4) = 128 CTAs, 512 threads = 16 warps.
// PAIRED staging + producer-only-waits (consumers bar.arrive; warp 0 bar.syncs
// and refills; alternating barrier IDs bound skew at one pair).
__global__ __launch_bounds__(512, 1) void kan_main(const float* __restrict__ x,
                                                   float* __restrict__ part) {
    extern __shared__ char smraw[];
    float* sx = reinterpret_cast<float*>(smraw + 2 * PAIRB);          // DCH * BT floats
    uint32_t mbarBase = (uint32_t)__cvta_generic_to_shared(
        smraw + 2 * PAIRB + DCH * BT * 4);                            // 2 x 8B mbarriers
    uint32_t sb = (uint32_t)__cvta_generic_to_shared(smraw);

    const int bt = blockIdx.x, dc = blockIdx.y;
    const int tid = threadIdx.x;
    const int w = tid >> 5, lane = tid & 31;
    const int dbase = dc * DCH;
    const int b0g = bt * BT;

    // load x tile [BT][DCH] -> sx[dd][b_local]   (overlaps prep via PDL)
    for (int e = tid; e < BT * 4; e += 512) {
        int bl = e >> 2, seg = e & 3;
        float4 v = *reinterpret_cast<const float4*>(x + (size_t)(b0g + bl) * DD + dbase + seg * 4);
        sx[(seg * 4 + 0) * BT + bl] = v.x;
        sx[(seg * 4 + 1) * BT + bl] = v.y;
        sx[(seg * 4 + 2) * BT + bl] = v.z;
        sx[(seg * 4 + 3) * BT + bl] = v.w;
    }

    if (tid == 0) {
        mbar_init(mbarBase, 1);
        mbar_init(mbarBase + 8, 1);
    }
    __syncthreads();   // mbar init visible + sx done

    auto issue = [&](int pair, int which) {
        uint32_t mb = mbarBase + (uint32_t)which * 8;
        mbar_expect_tx(mb, PAIRB);
        bulk_g2s(sb + (uint32_t)which * PAIRB,
                 g_Ph + (size_t)(dbase + 2 * pair) * SLICE, PAIRB, mb);
    };
    if (tid == 0) {
        cudaGridDependencySynchronize();   // wait for kan_prep grid before reading g_Ph
        issue(0, 0); issue(1, 1);
    }

    u64 acc[16];
    #pragma unroll
    for (int i = 0; i < 16; i++) acc[i] = 0ULL;   // bit pattern of (0.f, 0.f)

    const char* laneBase = smraw + (size_t)lane * 16;

    for (int p = 0; p < NPAIR; p++) {
        int which = p & 1;
        mbar_wait(mbarBase + which * 8, (uint32_t)(p >> 1) & 1);

        #pragma unroll
        for (int sub = 0; sub < 2; sub++) {
            const int dd = 2 * p + sub;
            const char* cur = laneBase + (size_t)which * PAIRB + (size_t)sub * SLICE_BYTES;

            // per-lane (jj, u) for this warp's 16 b's (lanes 16-31 mirror 0-15),
            // packed as (byte_off << 16) | fp16(u), byte_off = jj*512 (fits 16 bits)
            float xv = sx[dd * BT + (w << 4) + (lane & 15)];
            float t = (xv + 2.0f) * 15.75f;
            float f = fminf(fmaxf(floorf(t), 0.0f), 62.0f);
            int jj; float u;
            if (t < 0.0f)       { jj = 0;  u = t; }
            else if (t > 63.0f) { jj = 64; u = t - 63.0f; }
            else                { jj = (int)f + 1; u = t - f; }
            unsigned pk = ((unsigned)(jj << 9) << 16) |
                          (unsigned)__half_as_ushort(__float2half_rn(u));

            #pragma unroll
            for (int i = 0; i < 16; i++) {
                unsigned pv  = __shfl_sync(0xffffffffu, pk, i);
                unsigned off = pv >> 16;                       // byte offset of row
                unsigned u2b = __byte_perm(pv, pv, 0x1010);    // half2(u, u)
                uint4 q = *reinterpret_cast<const uint4*>(cur + off);
                __half2 uu = *reinterpret_cast<__half2*>(&u2b);
                __half2 hc0 = *reinterpret_cast<__half2*>(&q.x);
                __half2 hc1 = *reinterpret_cast<__half2*>(&q.y);
                __half2 hc2 = *reinterpret_cast<__half2*>(&q.z);
                __half2 hc3 = *reinterpret_cast<__half2*>(&q.w);
                __half2 r = __hfma2(hc3, uu, hc2);
                r = __hfma2(r, uu, hc1);
                r = __hfma2(r, uu, hc0);
                float2 rf = __half22float2(r);
                acc[i] = add2(acc[i], pk2(rf.x, rf.y));
            }
        }

        // producer-only-waits drain protocol (skip when no refill is needed)
        if (p + 2 < NPAIR) {
            int barid = 1 + (p & 1);
            if (w == 0) {
                bar_wait(barid);               // absorb skew in warp 0 only
                if (lane == 0) issue(p + 2, which);
            } else {
                bar_arrive(barid);             // non-blocking release
            }
        }
    }

    // partials: part[dc][b][o]
    float* pdst = part + ((size_t)dc * BB + b0g + (w << 4)) * OO;
    #pragma unroll
    for (int i = 0; i < 16; i++) {
        float2 v = upk2(acc[i]);
        pdst[i * OO + lane]      = v.x;
        pdst[i * OO + 32 + lane] = v.y;
    }
}

// ---------------------------------------------------------------- split-K reduce + bias (float4, PDL)
__global__ void kan_reduce(const float* __restrict__ part, const float* __restrict__ bias,
                           float* __restrict__ out) {
    cudaGridDependencySynchronize();   // wait for kan_main grid before reading partials
    int idx = blockIdx.x * 256 + threadIdx.x;     // over B*O/4
    const float4* p4 = reinterpret_cast<const float4*>(part);
    float4 s = reinterpret_cast<const float4*>(bias)[idx & 15];
    #pragma unroll
    for (int c = 0; c < NDC; c++) {
        float4 v = p4[(size_t)c * (BB * OO / 4) + idx];
        s.x += v.x; s.y += v.y; s.z += v.z; s.w += v.w;
    }
    reinterpret_cast<float4*>(out)[idx] = s;
}

// ---------------------------------------------------------------- launch
extern "C" void kernel_launch(void* const* d_in, const int* in_sizes, int n_in,
                              void* d_out, int out_size) {
    const float* x      = (const float*)d_in[0];   // [8192, 64]
    const float* coeffs = (const float*)d_in[1];   // [64, 64, 64]
    const float* bias   = (const float*)d_in[2];   // [64]
    float* out = (float*)d_out;                    // [8192, 64]

    float* prt; cudaGetSymbolAddress((void**)&prt, g_part);

    const int smem_main = 2 * PAIRB + DCH * BT * 4 + 16;   // 149520
    cudaFuncSetAttribute(kan_main, cudaFuncAttributeMaxDynamicSharedMemorySize, smem_main);

    // kernel 1: single-wave prep (128 CTAs, triggers PDL immediately)
    kan_prep<<<dim3(DD, 2), 512>>>(coeffs);

    // kernel 2: PDL launch (overlaps prep; gridsync gates g_Ph reads)
    cudaLaunchAttribute attr[1];
    attr[0].id = cudaLaunchAttributeProgrammaticStreamSerialization;
    attr[0].val.programmaticStreamSerializationAllowed = 1;

    cudaLaunchConfig_t cfg = {};
    cfg.gridDim = dim3(NBT, NDC, 1);
    cfg.blockDim = dim3(512, 1, 1);
    cfg.dynamicSmemBytes = smem_main;
    cfg.stream = 0;
    cfg.attrs = attr;
    cfg.numAttrs = 1;
    cudaLaunchKernelEx(&cfg, kan_main, x, prt);

    // kernel 3: PDL launch (hides launch latency; gridsync gates partials reads)
    cudaLaunchConfig_t cfg2 = {};
    cfg2.gridDim = dim3((BB * OO / 4) / 256, 1, 1);
    cfg2.blockDim = dim3(256, 1, 1);
    cfg2.dynamicSmemBytes = 0;
    cfg2.stream = 0;
    cfg2.attrs = attr;
    cfg2.numAttrs = 1;
    cudaLaunchKernelEx(&cfg2, kan_reduce, (const float*)prt, bias, out);
}